// round 8
// baseline (speedup 1.0000x reference)
#include <cuda_runtime.h>
#include <cuda_fp16.h>
#include <cstdint>

static const int BATCH = 8;
static const int TQ    = 2048;
static const int TK    = 2048;
static const int DIM   = 1024;

// Scratch buffers
__device__ float    g_energy[(size_t)8 * 2048 * 2048];        // 128 MB
__device__ __half   g_ph[(size_t)8 * 2048 * 2048];            // 64 MB (P*1024 in f16)
__device__ uint32_t g_qhi[(size_t)8 * 2048 * 1024 / 2];       // 32 MB (bf16x2)
__device__ uint32_t g_qlo[(size_t)8 * 2048 * 1024 / 2];
__device__ uint32_t g_khi[(size_t)8 * 2048 * 1024 / 2];
__device__ uint32_t g_klo[(size_t)8 * 2048 * 1024 / 2];
__device__ uint32_t g_vh [(size_t)8 * 2048 * 1024 / 2];       // f16x2 of K (V role)

#define P_SCALE     1024.0f
#define P_SCALE_INV (1.0f / 1024.0f)

// ---------------------------------------------------------------------------
__device__ __forceinline__ uint32_t smem_u32(const void* p) {
    uint32_t a;
    asm("{ .reg .u64 t; cvta.to.shared.u64 t, %1; cvt.u32.u64 %0, t; }" : "=r"(a) : "l"(p));
    return a;
}

__device__ __forceinline__ void mma_bf16(float* d, const uint32_t* a, uint32_t b0, uint32_t b1) {
    asm volatile(
        "mma.sync.aligned.m16n8k16.row.col.f32.bf16.bf16.f32 "
        "{%0,%1,%2,%3}, {%4,%5,%6,%7}, {%8,%9}, {%0,%1,%2,%3};"
        : "+f"(d[0]), "+f"(d[1]), "+f"(d[2]), "+f"(d[3])
        : "r"(a[0]), "r"(a[1]), "r"(a[2]), "r"(a[3]), "r"(b0), "r"(b1));
}
__device__ __forceinline__ void mma_f16(float* d, const uint32_t* a, uint32_t b0, uint32_t b1) {
    asm volatile(
        "mma.sync.aligned.m16n8k16.row.col.f32.f16.f16.f32 "
        "{%0,%1,%2,%3}, {%4,%5,%6,%7}, {%8,%9}, {%0,%1,%2,%3};"
        : "+f"(d[0]), "+f"(d[1]), "+f"(d[2]), "+f"(d[3])
        : "r"(a[0]), "r"(a[1]), "r"(a[2]), "r"(a[3]), "r"(b0), "r"(b1));
}

#define LDSM4(r, a) \
    asm volatile("ldmatrix.sync.aligned.m8n8.x4.shared.b16 {%0,%1,%2,%3}, [%4];" \
                 : "=r"((r)[0]), "=r"((r)[1]), "=r"((r)[2]), "=r"((r)[3]) : "r"(a))
#define LDSM4T(r, a) \
    asm volatile("ldmatrix.sync.aligned.m8n8.x4.trans.shared.b16 {%0,%1,%2,%3}, [%4];" \
                 : "=r"((r)[0]), "=r"((r)[1]), "=r"((r)[2]), "=r"((r)[3]) : "r"(a))

#define CP16(dst, src) \
    asm volatile("cp.async.cg.shared.global [%0], [%1], 16;" :: "r"(dst), "l"(src))
#define CP_COMMIT() asm volatile("cp.async.commit_group;")
#define CP_WAIT2()  asm volatile("cp.async.wait_group 2;")

// Dekker split of 4 floats into bf16x2 hi/lo pairs (memory order x,y / z,w)
__device__ __forceinline__ void bf16_split_pack(float4 v, uint32_t& h01, uint32_t& h23,
                                                uint32_t& l01, uint32_t& l23) {
    asm("cvt.rn.bf16x2.f32 %0, %1, %2;" : "=r"(h01) : "f"(v.y), "f"(v.x));
    asm("cvt.rn.bf16x2.f32 %0, %1, %2;" : "=r"(h23) : "f"(v.w), "f"(v.z));
    float hx = __uint_as_float(h01 << 16);
    float hy = __uint_as_float(h01 & 0xFFFF0000u);
    float hz = __uint_as_float(h23 << 16);
    float hw = __uint_as_float(h23 & 0xFFFF0000u);
    asm("cvt.rn.bf16x2.f32 %0, %1, %2;" : "=r"(l01) : "f"(v.y - hy), "f"(v.x - hx));
    asm("cvt.rn.bf16x2.f32 %0, %1, %2;" : "=r"(l23) : "f"(v.w - hw), "f"(v.z - hz));
}

// ---------------------------------------------------------------------------
// Pre-pass: element-wise splits
// ---------------------------------------------------------------------------
__global__ __launch_bounds__(256) void split_q_kernel(const float* __restrict__ Q,
                                                      uint32_t* __restrict__ qhi,
                                                      uint32_t* __restrict__ qlo)
{
    size_t i = (size_t)blockIdx.x * 256 + threadIdx.x;
    float4 v = reinterpret_cast<const float4*>(Q)[i];
    uint32_t h01, h23, l01, l23;
    bf16_split_pack(v, h01, h23, l01, l23);
    reinterpret_cast<uint2*>(qhi)[i] = make_uint2(h01, h23);
    reinterpret_cast<uint2*>(qlo)[i] = make_uint2(l01, l23);
}

__global__ __launch_bounds__(256) void split_k_kernel(const float* __restrict__ Km,
                                                      uint32_t* __restrict__ khi,
                                                      uint32_t* __restrict__ klo,
                                                      uint32_t* __restrict__ vh)
{
    size_t i = (size_t)blockIdx.x * 256 + threadIdx.x;
    float4 v = reinterpret_cast<const float4*>(Km)[i];
    uint32_t h01, h23, l01, l23;
    bf16_split_pack(v, h01, h23, l01, l23);
    reinterpret_cast<uint2*>(khi)[i] = make_uint2(h01, h23);
    reinterpret_cast<uint2*>(klo)[i] = make_uint2(l01, l23);
    __half2 w0 = __floats2half2_rn(v.x, v.y);
    __half2 w1 = __floats2half2_rn(v.z, v.w);
    reinterpret_cast<uint2*>(vh)[i] =
        make_uint2(*reinterpret_cast<uint32_t*>(&w0), *reinterpret_cast<uint32_t*>(&w1));
}

// ---------------------------------------------------------------------------
// QK: E tile [128x128] = Qsplit @ Ksplit^T (3-term bf16). 256 thr, 2 CTA/SM.
// 4-stage cp.async pipeline. Stage = AH(4K) AL(4K) BH(4K) BL(4K) = 16KB.
// MMA issue order: term-major (16 independent HMMAs between acc reuses).
// ---------------------------------------------------------------------------
#define QK_STAGE 16384
#define QK_SMEM  (4 * QK_STAGE)

__global__ __launch_bounds__(256, 2) void qk_kernel(const uint16_t* __restrict__ Qhi,
                                                    const uint16_t* __restrict__ Qlo,
                                                    const uint16_t* __restrict__ Khi,
                                                    const uint16_t* __restrict__ Klo,
                                                    float* __restrict__ E)
{
    extern __shared__ uint32_t dsm[];
    const uint32_t sb = smem_u32(dsm);

    const int tid = threadIdx.x, wid = tid >> 5, lane = tid & 31;
    const int gid = lane >> 2, tig = lane & 3;
    const int wm = (wid >> 1) * 32, wn = (wid & 1) * 64;
    const int row0 = blockIdx.y * 128, col0 = blockIdx.x * 128;

    const size_t bo = (size_t)blockIdx.z * TQ * DIM;
    const uint16_t* gAh = Qhi + bo;
    const uint16_t* gAl = Qlo + bo;
    const uint16_t* gBh = Khi + bo;
    const uint16_t* gBl = Klo + bo;
    float* Eb = E + (size_t)blockIdx.z * TQ * TK;

    const int lr = tid >> 1, lch = tid & 1;
    const uint32_t ldst = (uint32_t)(lr * 32 + ((lch ^ ((lr >> 2) & 1)) * 16));
    const uint16_t* srcAh = gAh + (size_t)(row0 + lr) * DIM + lch * 8;
    const uint16_t* srcAl = gAl + (size_t)(row0 + lr) * DIM + lch * 8;
    const uint16_t* srcBh = gBh + (size_t)(col0 + lr) * DIM + lch * 8;
    const uint16_t* srcBl = gBl + (size_t)(col0 + lr) * DIM + lch * 8;

    const int row_l = (lane & 7) + ((lane >> 3) & 1) * 8;
    const int chnk  = (lane >> 4) & 1;
    uint32_t aoff[2], boff[4];
    #pragma unroll
    for (int mi = 0; mi < 2; mi++) {
        int m = wm + mi * 16 + row_l;
        aoff[mi] = (uint32_t)(m * 32 + (((chnk << 2) ^ (((m >> 2) & 1) << 2)) << 2));
    }
    #pragma unroll
    for (int g = 0; g < 4; g++) {
        int n = wn + g * 16 + row_l;
        boff[g] = (uint32_t)(n * 32 + (((chnk << 2) ^ (((n >> 2) & 1) << 2)) << 2));
    }

    float acc[2][8][4];
    #pragma unroll
    for (int i = 0; i < 2; i++)
        #pragma unroll
        for (int j = 0; j < 8; j++)
            #pragma unroll
            for (int c = 0; c < 4; c++) acc[i][j][c] = 0.0f;

    const int NIT = DIM / 16;  // 64

    auto issue = [&](int it) {
        uint32_t d = sb + (it & 3) * QK_STAGE + ldst;
        size_t go = (size_t)it * 16;
        CP16(d,         srcAh + go);
        CP16(d + 4096,  srcAl + go);
        CP16(d + 8192,  srcBh + go);
        CP16(d + 12288, srcBl + go);
        CP_COMMIT();
    };

    issue(0); issue(1); issue(2);

    for (int it = 0; it < NIT; it++) {
        CP_WAIT2();
        __syncthreads();
        if (it + 3 < NIT) issue(it + 3);

        const uint32_t base = sb + (it & 3) * QK_STAGE;
        uint32_t aH[2][4], aL[2][4], bh[4][4], bl[4][4];
        LDSM4(aH[0], base + aoff[0]);
        LDSM4(aH[1], base + aoff[1]);
        LDSM4(aL[0], base + 4096 + aoff[0]);
        LDSM4(aL[1], base + 4096 + aoff[1]);
        #pragma unroll
        for (int g = 0; g < 4; g++) {
            LDSM4(bh[g], base + 8192 + boff[g]);
            LDSM4(bl[g], base + 12288 + boff[g]);
        }

        // term HH: all 16 accs once
        #pragma unroll
        for (int g = 0; g < 4; g++)
            #pragma unroll
            for (int mi = 0; mi < 2; mi++) {
                mma_bf16(acc[mi][2 * g],     aH[mi], bh[g][0], bh[g][2]);
                mma_bf16(acc[mi][2 * g + 1], aH[mi], bh[g][1], bh[g][3]);
            }
        // term HL
        #pragma unroll
        for (int g = 0; g < 4; g++)
            #pragma unroll
            for (int mi = 0; mi < 2; mi++) {
                mma_bf16(acc[mi][2 * g],     aH[mi], bl[g][0], bl[g][2]);
                mma_bf16(acc[mi][2 * g + 1], aH[mi], bl[g][1], bl[g][3]);
            }
        // term LH
        #pragma unroll
        for (int g = 0; g < 4; g++)
            #pragma unroll
            for (int mi = 0; mi < 2; mi++) {
                mma_bf16(acc[mi][2 * g],     aL[mi], bh[g][0], bh[g][2]);
                mma_bf16(acc[mi][2 * g + 1], aL[mi], bh[g][1], bh[g][3]);
            }
    }

    #pragma unroll
    for (int mi = 0; mi < 2; mi++) {
        #pragma unroll
        for (int ni = 0; ni < 8; ni++) {
            int r = row0 + wm + mi * 16 + gid;
            int c = col0 + wn + ni * 8 + 2 * tig;
            *reinterpret_cast<float2*>(&Eb[(size_t)r * TK + c]) =
                make_float2(acc[mi][ni][0], acc[mi][ni][1]);
            *reinterpret_cast<float2*>(&Eb[(size_t)(r + 8) * TK + c]) =
                make_float2(acc[mi][ni][2], acc[mi][ni][3]);
        }
    }
}

// ---------------------------------------------------------------------------
// Softmax: read E f32 row, write P*1024 as f16 (avoids f16 subnormal band).
// ---------------------------------------------------------------------------
__global__ __launch_bounds__(256) void softmax_f16_kernel(const float* __restrict__ E,
                                                          __half* __restrict__ P)
{
    const float4* row = reinterpret_cast<const float4*>(E + (size_t)blockIdx.x * TK);
    const int t = threadIdx.x;

    float4 v0 = row[t];
    float4 v1 = row[t + 256];

    float m = fmaxf(fmaxf(fmaxf(v0.x, v0.y), fmaxf(v0.z, v0.w)),
                    fmaxf(fmaxf(v1.x, v1.y), fmaxf(v1.z, v1.w)));

    __shared__ float red[8];
    #pragma unroll
    for (int o = 16; o > 0; o >>= 1) m = fmaxf(m, __shfl_xor_sync(0xFFFFFFFFu, m, o));
    if ((t & 31) == 0) red[t >> 5] = m;
    __syncthreads();
    m = red[0];
    #pragma unroll
    for (int w = 1; w < 8; w++) m = fmaxf(m, red[w]);

    float4 e0, e1;
    e0.x = __expf(v0.x - m); e0.y = __expf(v0.y - m);
    e0.z = __expf(v0.z - m); e0.w = __expf(v0.w - m);
    e1.x = __expf(v1.x - m); e1.y = __expf(v1.y - m);
    e1.z = __expf(v1.z - m); e1.w = __expf(v1.w - m);

    float s = (e0.x + e0.y + e0.z + e0.w) + (e1.x + e1.y + e1.z + e1.w);
    #pragma unroll
    for (int o = 16; o > 0; o >>= 1) s += __shfl_xor_sync(0xFFFFFFFFu, s, o);
    __syncthreads();
    if ((t & 31) == 0) red[t >> 5] = s;
    __syncthreads();
    s = 0.0f;
    #pragma unroll
    for (int w = 0; w < 8; w++) s += red[w];

    float inv = P_SCALE / s;   // scaled by 2^10: keeps f16 P out of subnormals
    e0.x *= inv; e0.y *= inv; e0.z *= inv; e0.w *= inv;
    e1.x *= inv; e1.y *= inv; e1.z *= inv; e1.w *= inv;

    __half* ph = P + (size_t)blockIdx.x * TK;

    __half2 h0 = __floats2half2_rn(e0.x, e0.y);
    __half2 h1 = __floats2half2_rn(e0.z, e0.w);
    uint2 H;
    H.x = *reinterpret_cast<uint32_t*>(&h0); H.y = *reinterpret_cast<uint32_t*>(&h1);
    *reinterpret_cast<uint2*>(&ph[4 * t]) = H;
    h0 = __floats2half2_rn(e1.x, e1.y);
    h1 = __floats2half2_rn(e1.z, e1.w);
    H.x = *reinterpret_cast<uint32_t*>(&h0); H.y = *reinterpret_cast<uint32_t*>(&h1);
    *reinterpret_cast<uint2*>(&ph[1024 + 4 * t]) = H;
}

// ---------------------------------------------------------------------------
// PV: O tile [128x128] = Pscaled_f16[128x2048] @ V_f16[2048x128], single term.
// Epilogue multiplies by 2^-10. 4-stage cp.async. Stage = P(4K) V(4K) = 8KB.
// ---------------------------------------------------------------------------
#define PV_STAGE 8192
#define PV_SMEM  (4 * PV_STAGE)

__global__ __launch_bounds__(256, 2) void pv_kernel(const uint16_t* __restrict__ Ph,
                                                    const uint16_t* __restrict__ Vh,
                                                    float* __restrict__ O)
{
    extern __shared__ uint32_t dsm[];
    const uint32_t sb = smem_u32(dsm);

    const int tid = threadIdx.x, wid = tid >> 5, lane = tid & 31;
    const int gid = lane >> 2, tig = lane & 3;
    const int wm = (wid >> 1) * 32, wn = (wid & 1) * 64;
    const int row0 = blockIdx.y * 128, col0 = blockIdx.x * 128;

    const uint16_t* PhB = Ph + (size_t)blockIdx.z * TQ * TK;
    const uint16_t* VhB = Vh + (size_t)blockIdx.z * TK * DIM;
    float*          Ob  = O  + (size_t)blockIdx.z * TQ * DIM;

    const int lr = tid >> 1, lch = tid & 1;
    const uint32_t pdst = (uint32_t)(lr * 32 + ((lch ^ ((lr >> 2) & 1)) * 16));
    const uint16_t* srcPh = PhB + (size_t)(row0 + lr) * TK + lch * 8;
    const int vr = tid >> 4, vc = tid & 15;
    const uint32_t vdst = (uint32_t)(vr * 256 + (((vc & 8) | ((vc ^ vr) & 7)) * 16));
    const uint16_t* srcV = VhB + (size_t)vr * DIM + col0 + vc * 8;

    const int row_l = (lane & 7) + ((lane >> 3) & 1) * 8;
    const int chnk  = (lane >> 4) & 1;
    uint32_t aoff[2], boff[4];
    #pragma unroll
    for (int mi = 0; mi < 2; mi++) {
        int m = wm + mi * 16 + row_l;
        aoff[mi] = (uint32_t)(m * 32 + (((chnk << 2) ^ (((m >> 2) & 1) << 2)) << 2));
    }
    #pragma unroll
    for (int g = 0; g < 4; g++) {
        int nch = ((wn + g * 16) >> 3) + chnk;
        int cl  = (nch & 8) | ((nch ^ (row_l & 7)) & 7);
        boff[g] = (uint32_t)(row_l * 256 + cl * 16);
    }

    float acc[2][8][4];
    #pragma unroll
    for (int i = 0; i < 2; i++)
        #pragma unroll
        for (int j = 0; j < 8; j++)
            #pragma unroll
            for (int c = 0; c < 4; c++) acc[i][j][c] = 0.0f;

    const int NIT = TK / 16;  // 128

    auto issue = [&](int it) {
        uint32_t base = sb + (it & 3) * PV_STAGE;
        size_t go = (size_t)it * 16;
        CP16(base + pdst,        srcPh + go);
        CP16(base + 4096 + vdst, srcV + go * DIM);
        CP_COMMIT();
    };

    issue(0); issue(1); issue(2);

    for (int it = 0; it < NIT; it++) {
        CP_WAIT2();
        __syncthreads();
        if (it + 3 < NIT) issue(it + 3);

        const uint32_t base = sb + (it & 3) * PV_STAGE;
        uint32_t pH[2][4], bt[4][4];
        LDSM4(pH[0], base + aoff[0]);
        LDSM4(pH[1], base + aoff[1]);
        #pragma unroll
        for (int g = 0; g < 4; g++)
            LDSM4T(bt[g], base + 4096 + boff[g]);

        #pragma unroll
        for (int g = 0; g < 4; g++)
            #pragma unroll
            for (int mi = 0; mi < 2; mi++) {
                mma_f16(acc[mi][2 * g],     pH[mi], bt[g][0], bt[g][1]);
                mma_f16(acc[mi][2 * g + 1], pH[mi], bt[g][2], bt[g][3]);
            }
    }

    #pragma unroll
    for (int mi = 0; mi < 2; mi++) {
        #pragma unroll
        for (int ni = 0; ni < 8; ni++) {
            int r = row0 + wm + mi * 16 + gid;
            int c = col0 + wn + ni * 8 + 2 * tig;
            *reinterpret_cast<float2*>(&Ob[(size_t)r * DIM + c]) =
                make_float2(acc[mi][ni][0] * P_SCALE_INV, acc[mi][ni][1] * P_SCALE_INV);
            *reinterpret_cast<float2*>(&Ob[(size_t)(r + 8) * DIM + c]) =
                make_float2(acc[mi][ni][2] * P_SCALE_INV, acc[mi][ni][3] * P_SCALE_INV);
        }
    }
}

// ---------------------------------------------------------------------------
extern "C" void kernel_launch(void* const* d_in, const int* in_sizes, int n_in,
                              void* d_out, int out_size)
{
    const float* q   = (const float*)d_in[0];
    const float* key = (const float*)d_in[1];
    float*       out = (float*)d_out;

    float* energy = nullptr;
    __half* ph = nullptr;
    uint32_t *qhi, *qlo, *khi, *klo, *vh;
    cudaGetSymbolAddress((void**)&energy, g_energy);
    cudaGetSymbolAddress((void**)&ph, g_ph);
    cudaGetSymbolAddress((void**)&qhi, g_qhi);
    cudaGetSymbolAddress((void**)&qlo, g_qlo);
    cudaGetSymbolAddress((void**)&khi, g_khi);
    cudaGetSymbolAddress((void**)&klo, g_klo);
    cudaGetSymbolAddress((void**)&vh,  g_vh);

    cudaFuncSetAttribute(qk_kernel, cudaFuncAttributeMaxDynamicSharedMemorySize, QK_SMEM);
    cudaFuncSetAttribute(pv_kernel, cudaFuncAttributeMaxDynamicSharedMemorySize, PV_SMEM);

    const int nv4 = (int)((size_t)BATCH * TQ * DIM / 4 / 256);  // 16384 blocks
    split_q_kernel<<<nv4, 256>>>(q, qhi, qlo);
    split_k_kernel<<<nv4, 256>>>(key, khi, klo, vh);

    dim3 g1(TK / 128, TQ / 128, BATCH);
    qk_kernel<<<g1, 256, QK_SMEM>>>((const uint16_t*)qhi, (const uint16_t*)qlo,
                                    (const uint16_t*)khi, (const uint16_t*)klo, energy);

    softmax_f16_kernel<<<BATCH * TQ, 256>>>(energy, ph);

    dim3 g2(DIM / 128, TQ / 128, BATCH);
    pv_kernel<<<g2, 256, PV_SMEM>>>((const uint16_t*)ph, (const uint16_t*)vh, out);
}

// round 9
// speedup vs baseline: 1.5638x; 1.5638x over previous
#include <cuda_runtime.h>
#include <cuda_fp16.h>
#include <cstdint>

static const int BATCH = 8;
static const int TQ    = 2048;
static const int TK    = 2048;
static const int DIM   = 1024;

// Scratch buffers
__device__ float    g_energy[(size_t)8 * 2048 * 2048];        // 128 MB
__device__ __half   g_ph[(size_t)8 * 2048 * 2048];            // 64 MB (P*1024 in f16)
__device__ uint32_t g_qhi[(size_t)8 * 2048 * 1024 / 2];       // 32 MB (bf16x2)
__device__ uint32_t g_qlo[(size_t)8 * 2048 * 1024 / 2];
__device__ uint32_t g_khi[(size_t)8 * 2048 * 1024 / 2];
__device__ uint32_t g_klo[(size_t)8 * 2048 * 1024 / 2];
__device__ uint32_t g_vh [(size_t)8 * 2048 * 1024 / 2];       // f16x2 of K (V role)

#define P_SCALE     1024.0f
#define P_SCALE_INV (1.0f / 1024.0f)

// ---------------------------------------------------------------------------
__device__ __forceinline__ uint32_t smem_u32(const void* p) {
    uint32_t a;
    asm("{ .reg .u64 t; cvta.to.shared.u64 t, %1; cvt.u32.u64 %0, t; }" : "=r"(a) : "l"(p));
    return a;
}

__device__ __forceinline__ void mma_bf16(float* d, const uint32_t* a, uint32_t b0, uint32_t b1) {
    asm volatile(
        "mma.sync.aligned.m16n8k16.row.col.f32.bf16.bf16.f32 "
        "{%0,%1,%2,%3}, {%4,%5,%6,%7}, {%8,%9}, {%0,%1,%2,%3};"
        : "+f"(d[0]), "+f"(d[1]), "+f"(d[2]), "+f"(d[3])
        : "r"(a[0]), "r"(a[1]), "r"(a[2]), "r"(a[3]), "r"(b0), "r"(b1));
}
__device__ __forceinline__ void mma_f16(float* d, const uint32_t* a, uint32_t b0, uint32_t b1) {
    asm volatile(
        "mma.sync.aligned.m16n8k16.row.col.f32.f16.f16.f32 "
        "{%0,%1,%2,%3}, {%4,%5,%6,%7}, {%8,%9}, {%0,%1,%2,%3};"
        : "+f"(d[0]), "+f"(d[1]), "+f"(d[2]), "+f"(d[3])
        : "r"(a[0]), "r"(a[1]), "r"(a[2]), "r"(a[3]), "r"(b0), "r"(b1));
}

#define LDSM4(r, a) \
    asm volatile("ldmatrix.sync.aligned.m8n8.x4.shared.b16 {%0,%1,%2,%3}, [%4];" \
                 : "=r"((r)[0]), "=r"((r)[1]), "=r"((r)[2]), "=r"((r)[3]) : "r"(a))
#define LDSM4T(r, a) \
    asm volatile("ldmatrix.sync.aligned.m8n8.x4.trans.shared.b16 {%0,%1,%2,%3}, [%4];" \
                 : "=r"((r)[0]), "=r"((r)[1]), "=r"((r)[2]), "=r"((r)[3]) : "r"(a))

#define CP16(dst, src) \
    asm volatile("cp.async.cg.shared.global [%0], [%1], 16;" :: "r"(dst), "l"(src))
#define CP_COMMIT() asm volatile("cp.async.commit_group;")
#define CP_WAIT2()  asm volatile("cp.async.wait_group 2;")

// Dekker split of 4 floats into bf16x2 hi/lo pairs (memory order x,y / z,w)
__device__ __forceinline__ void bf16_split_pack(float4 v, uint32_t& h01, uint32_t& h23,
                                                uint32_t& l01, uint32_t& l23) {
    asm("cvt.rn.bf16x2.f32 %0, %1, %2;" : "=r"(h01) : "f"(v.y), "f"(v.x));
    asm("cvt.rn.bf16x2.f32 %0, %1, %2;" : "=r"(h23) : "f"(v.w), "f"(v.z));
    float hx = __uint_as_float(h01 << 16);
    float hy = __uint_as_float(h01 & 0xFFFF0000u);
    float hz = __uint_as_float(h23 << 16);
    float hw = __uint_as_float(h23 & 0xFFFF0000u);
    asm("cvt.rn.bf16x2.f32 %0, %1, %2;" : "=r"(l01) : "f"(v.y - hy), "f"(v.x - hx));
    asm("cvt.rn.bf16x2.f32 %0, %1, %2;" : "=r"(l23) : "f"(v.w - hw), "f"(v.z - hz));
}

// ---------------------------------------------------------------------------
// Pre-pass: element-wise splits
// ---------------------------------------------------------------------------
__global__ __launch_bounds__(256) void split_q_kernel(const float* __restrict__ Q,
                                                      uint32_t* __restrict__ qhi,
                                                      uint32_t* __restrict__ qlo)
{
    size_t i = (size_t)blockIdx.x * 256 + threadIdx.x;
    float4 v = reinterpret_cast<const float4*>(Q)[i];
    uint32_t h01, h23, l01, l23;
    bf16_split_pack(v, h01, h23, l01, l23);
    reinterpret_cast<uint2*>(qhi)[i] = make_uint2(h01, h23);
    reinterpret_cast<uint2*>(qlo)[i] = make_uint2(l01, l23);
}

__global__ __launch_bounds__(256) void split_k_kernel(const float* __restrict__ Km,
                                                      uint32_t* __restrict__ khi,
                                                      uint32_t* __restrict__ klo,
                                                      uint32_t* __restrict__ vh)
{
    size_t i = (size_t)blockIdx.x * 256 + threadIdx.x;
    float4 v = reinterpret_cast<const float4*>(Km)[i];
    uint32_t h01, h23, l01, l23;
    bf16_split_pack(v, h01, h23, l01, l23);
    reinterpret_cast<uint2*>(khi)[i] = make_uint2(h01, h23);
    reinterpret_cast<uint2*>(klo)[i] = make_uint2(l01, l23);
    __half2 w0 = __floats2half2_rn(v.x, v.y);
    __half2 w1 = __floats2half2_rn(v.z, v.w);
    reinterpret_cast<uint2*>(vh)[i] =
        make_uint2(*reinterpret_cast<uint32_t*>(&w0), *reinterpret_cast<uint32_t*>(&w1));
}

// ---------------------------------------------------------------------------
// QK: E tile [128x128] = Qsplit @ Ksplit^T (3-term bf16). 256 thr, 2 CTA/SM.
// 4-stage cp.async pipeline. Stage = AH(4K) AL(4K) BH(4K) BL(4K) = 16KB.
// Inner loop: round-6 interleaved order (B frags consumed per group; no spills).
// ---------------------------------------------------------------------------
#define QK_STAGE 16384
#define QK_SMEM  (4 * QK_STAGE)

__global__ __launch_bounds__(256, 2) void qk_kernel(const uint16_t* __restrict__ Qhi,
                                                    const uint16_t* __restrict__ Qlo,
                                                    const uint16_t* __restrict__ Khi,
                                                    const uint16_t* __restrict__ Klo,
                                                    float* __restrict__ E)
{
    extern __shared__ uint32_t dsm[];
    const uint32_t sb = smem_u32(dsm);

    const int tid = threadIdx.x, wid = tid >> 5, lane = tid & 31;
    const int gid = lane >> 2, tig = lane & 3;
    const int wm = (wid >> 1) * 32, wn = (wid & 1) * 64;
    const int row0 = blockIdx.y * 128, col0 = blockIdx.x * 128;

    const size_t bo = (size_t)blockIdx.z * TQ * DIM;
    const uint16_t* gAh = Qhi + bo;
    const uint16_t* gAl = Qlo + bo;
    const uint16_t* gBh = Khi + bo;
    const uint16_t* gBl = Klo + bo;
    float* Eb = E + (size_t)blockIdx.z * TQ * TK;

    const int lr = tid >> 1, lch = tid & 1;
    const uint32_t ldst = (uint32_t)(lr * 32 + ((lch ^ ((lr >> 2) & 1)) * 16));
    const uint16_t* srcAh = gAh + (size_t)(row0 + lr) * DIM + lch * 8;
    const uint16_t* srcAl = gAl + (size_t)(row0 + lr) * DIM + lch * 8;
    const uint16_t* srcBh = gBh + (size_t)(col0 + lr) * DIM + lch * 8;
    const uint16_t* srcBl = gBl + (size_t)(col0 + lr) * DIM + lch * 8;

    const int row_l = (lane & 7) + ((lane >> 3) & 1) * 8;
    const int chnk  = (lane >> 4) & 1;
    uint32_t aoff[2], boff[4];
    #pragma unroll
    for (int mi = 0; mi < 2; mi++) {
        int m = wm + mi * 16 + row_l;
        aoff[mi] = (uint32_t)(m * 32 + (((chnk << 2) ^ (((m >> 2) & 1) << 2)) << 2));
    }
    #pragma unroll
    for (int g = 0; g < 4; g++) {
        int n = wn + g * 16 + row_l;
        boff[g] = (uint32_t)(n * 32 + (((chnk << 2) ^ (((n >> 2) & 1) << 2)) << 2));
    }

    float acc[2][8][4];
    #pragma unroll
    for (int i = 0; i < 2; i++)
        #pragma unroll
        for (int j = 0; j < 8; j++)
            #pragma unroll
            for (int c = 0; c < 4; c++) acc[i][j][c] = 0.0f;

    const int NIT = DIM / 16;  // 64

    auto issue = [&](int it) {
        uint32_t d = sb + (it & 3) * QK_STAGE + ldst;
        size_t go = (size_t)it * 16;
        CP16(d,         srcAh + go);
        CP16(d + 4096,  srcAl + go);
        CP16(d + 8192,  srcBh + go);
        CP16(d + 12288, srcBl + go);
        CP_COMMIT();
    };

    issue(0); issue(1); issue(2);

    for (int it = 0; it < NIT; it++) {
        CP_WAIT2();
        __syncthreads();
        if (it + 3 < NIT) issue(it + 3);

        const uint32_t base = sb + (it & 3) * QK_STAGE;
        uint32_t aH[2][4], aL[2][4];
        LDSM4(aH[0], base + aoff[0]);
        LDSM4(aH[1], base + aoff[1]);
        LDSM4(aL[0], base + 4096 + aoff[0]);
        LDSM4(aL[1], base + 4096 + aoff[1]);

        #pragma unroll
        for (int g = 0; g < 4; g++) {
            uint32_t bh[4], bl[4];
            LDSM4(bh, base + 8192 + boff[g]);
            LDSM4(bl, base + 12288 + boff[g]);
            #pragma unroll
            for (int mi = 0; mi < 2; mi++) {
                mma_bf16(acc[mi][2 * g],     aH[mi], bh[0], bh[2]);
                mma_bf16(acc[mi][2 * g],     aH[mi], bl[0], bl[2]);
                mma_bf16(acc[mi][2 * g],     aL[mi], bh[0], bh[2]);
                mma_bf16(acc[mi][2 * g + 1], aH[mi], bh[1], bh[3]);
                mma_bf16(acc[mi][2 * g + 1], aH[mi], bl[1], bl[3]);
                mma_bf16(acc[mi][2 * g + 1], aL[mi], bh[1], bh[3]);
            }
        }
    }

    #pragma unroll
    for (int mi = 0; mi < 2; mi++) {
        #pragma unroll
        for (int ni = 0; ni < 8; ni++) {
            int r = row0 + wm + mi * 16 + gid;
            int c = col0 + wn + ni * 8 + 2 * tig;
            *reinterpret_cast<float2*>(&Eb[(size_t)r * TK + c]) =
                make_float2(acc[mi][ni][0], acc[mi][ni][1]);
            *reinterpret_cast<float2*>(&Eb[(size_t)(r + 8) * TK + c]) =
                make_float2(acc[mi][ni][2], acc[mi][ni][3]);
        }
    }
}

// ---------------------------------------------------------------------------
// Softmax: read E f32 row, write P*1024 as f16 (avoids f16 subnormal band).
// ---------------------------------------------------------------------------
__global__ __launch_bounds__(256) void softmax_f16_kernel(const float* __restrict__ E,
                                                          __half* __restrict__ P)
{
    const float4* row = reinterpret_cast<const float4*>(E + (size_t)blockIdx.x * TK);
    const int t = threadIdx.x;

    float4 v0 = row[t];
    float4 v1 = row[t + 256];

    float m = fmaxf(fmaxf(fmaxf(v0.x, v0.y), fmaxf(v0.z, v0.w)),
                    fmaxf(fmaxf(v1.x, v1.y), fmaxf(v1.z, v1.w)));

    __shared__ float red[8];
    #pragma unroll
    for (int o = 16; o > 0; o >>= 1) m = fmaxf(m, __shfl_xor_sync(0xFFFFFFFFu, m, o));
    if ((t & 31) == 0) red[t >> 5] = m;
    __syncthreads();
    m = red[0];
    #pragma unroll
    for (int w = 1; w < 8; w++) m = fmaxf(m, red[w]);

    float4 e0, e1;
    e0.x = __expf(v0.x - m); e0.y = __expf(v0.y - m);
    e0.z = __expf(v0.z - m); e0.w = __expf(v0.w - m);
    e1.x = __expf(v1.x - m); e1.y = __expf(v1.y - m);
    e1.z = __expf(v1.z - m); e1.w = __expf(v1.w - m);

    float s = (e0.x + e0.y + e0.z + e0.w) + (e1.x + e1.y + e1.z + e1.w);
    #pragma unroll
    for (int o = 16; o > 0; o >>= 1) s += __shfl_xor_sync(0xFFFFFFFFu, s, o);
    __syncthreads();
    if ((t & 31) == 0) red[t >> 5] = s;
    __syncthreads();
    s = 0.0f;
    #pragma unroll
    for (int w = 0; w < 8; w++) s += red[w];

    float inv = P_SCALE / s;   // scaled by 2^10: keeps f16 P out of subnormals
    e0.x *= inv; e0.y *= inv; e0.z *= inv; e0.w *= inv;
    e1.x *= inv; e1.y *= inv; e1.z *= inv; e1.w *= inv;

    __half* ph = P + (size_t)blockIdx.x * TK;

    __half2 h0 = __floats2half2_rn(e0.x, e0.y);
    __half2 h1 = __floats2half2_rn(e0.z, e0.w);
    uint2 H;
    H.x = *reinterpret_cast<uint32_t*>(&h0); H.y = *reinterpret_cast<uint32_t*>(&h1);
    *reinterpret_cast<uint2*>(&ph[4 * t]) = H;
    h0 = __floats2half2_rn(e1.x, e1.y);
    h1 = __floats2half2_rn(e1.z, e1.w);
    H.x = *reinterpret_cast<uint32_t*>(&h0); H.y = *reinterpret_cast<uint32_t*>(&h1);
    *reinterpret_cast<uint2*>(&ph[1024 + 4 * t]) = H;
}

// ---------------------------------------------------------------------------
// PV: O tile [128x128] = Pscaled_f16[128x2048] @ V_f16[2048x128], single term.
// Epilogue multiplies by 2^-10. 4-stage cp.async. Stage = P(4K) V(4K) = 8KB.
// ---------------------------------------------------------------------------
#define PV_STAGE 8192
#define PV_SMEM  (4 * PV_STAGE)

__global__ __launch_bounds__(256, 2) void pv_kernel(const uint16_t* __restrict__ Ph,
                                                    const uint16_t* __restrict__ Vh,
                                                    float* __restrict__ O)
{
    extern __shared__ uint32_t dsm[];
    const uint32_t sb = smem_u32(dsm);

    const int tid = threadIdx.x, wid = tid >> 5, lane = tid & 31;
    const int gid = lane >> 2, tig = lane & 3;
    const int wm = (wid >> 1) * 32, wn = (wid & 1) * 64;
    const int row0 = blockIdx.y * 128, col0 = blockIdx.x * 128;

    const uint16_t* PhB = Ph + (size_t)blockIdx.z * TQ * TK;
    const uint16_t* VhB = Vh + (size_t)blockIdx.z * TK * DIM;
    float*          Ob  = O  + (size_t)blockIdx.z * TQ * DIM;

    const int lr = tid >> 1, lch = tid & 1;
    const uint32_t pdst = (uint32_t)(lr * 32 + ((lch ^ ((lr >> 2) & 1)) * 16));
    const uint16_t* srcPh = PhB + (size_t)(row0 + lr) * TK + lch * 8;
    const int vr = tid >> 4, vc = tid & 15;
    const uint32_t vdst = (uint32_t)(vr * 256 + (((vc & 8) | ((vc ^ vr) & 7)) * 16));
    const uint16_t* srcV = VhB + (size_t)vr * DIM + col0 + vc * 8;

    const int row_l = (lane & 7) + ((lane >> 3) & 1) * 8;
    const int chnk  = (lane >> 4) & 1;
    uint32_t aoff[2], boff[4];
    #pragma unroll
    for (int mi = 0; mi < 2; mi++) {
        int m = wm + mi * 16 + row_l;
        aoff[mi] = (uint32_t)(m * 32 + (((chnk << 2) ^ (((m >> 2) & 1) << 2)) << 2));
    }
    #pragma unroll
    for (int g = 0; g < 4; g++) {
        int nch = ((wn + g * 16) >> 3) + chnk;
        int cl  = (nch & 8) | ((nch ^ (row_l & 7)) & 7);
        boff[g] = (uint32_t)(row_l * 256 + cl * 16);
    }

    float acc[2][8][4];
    #pragma unroll
    for (int i = 0; i < 2; i++)
        #pragma unroll
        for (int j = 0; j < 8; j++)
            #pragma unroll
            for (int c = 0; c < 4; c++) acc[i][j][c] = 0.0f;

    const int NIT = TK / 16;  // 128

    auto issue = [&](int it) {
        uint32_t base = sb + (it & 3) * PV_STAGE;
        size_t go = (size_t)it * 16;
        CP16(base + pdst,        srcPh + go);
        CP16(base + 4096 + vdst, srcV + go * DIM);
        CP_COMMIT();
    };

    issue(0); issue(1); issue(2);

    for (int it = 0; it < NIT; it++) {
        CP_WAIT2();
        __syncthreads();
        if (it + 3 < NIT) issue(it + 3);

        const uint32_t base = sb + (it & 3) * PV_STAGE;
        uint32_t pH[2][4];
        LDSM4(pH[0], base + aoff[0]);
        LDSM4(pH[1], base + aoff[1]);

        #pragma unroll
        for (int g = 0; g < 4; g++) {
            uint32_t bt[4];
            LDSM4T(bt, base + 4096 + boff[g]);
            #pragma unroll
            for (int mi = 0; mi < 2; mi++) {
                mma_f16(acc[mi][2 * g],     pH[mi], bt[0], bt[1]);
                mma_f16(acc[mi][2 * g + 1], pH[mi], bt[2], bt[3]);
            }
        }
    }

    #pragma unroll
    for (int mi = 0; mi < 2; mi++) {
        #pragma unroll
        for (int ni = 0; ni < 8; ni++) {
            int r = row0 + wm + mi * 16 + gid;
            int c = col0 + wn + ni * 8 + 2 * tig;
            *reinterpret_cast<float2*>(&Ob[(size_t)r * DIM + c]) =
                make_float2(acc[mi][ni][0] * P_SCALE_INV, acc[mi][ni][1] * P_SCALE_INV);
            *reinterpret_cast<float2*>(&Ob[(size_t)(r + 8) * DIM + c]) =
                make_float2(acc[mi][ni][2] * P_SCALE_INV, acc[mi][ni][3] * P_SCALE_INV);
        }
    }
}

// ---------------------------------------------------------------------------
extern "C" void kernel_launch(void* const* d_in, const int* in_sizes, int n_in,
                              void* d_out, int out_size)
{
    const float* q   = (const float*)d_in[0];
    const float* key = (const float*)d_in[1];
    float*       out = (float*)d_out;

    float* energy = nullptr;
    __half* ph = nullptr;
    uint32_t *qhi, *qlo, *khi, *klo, *vh;
    cudaGetSymbolAddress((void**)&energy, g_energy);
    cudaGetSymbolAddress((void**)&ph, g_ph);
    cudaGetSymbolAddress((void**)&qhi, g_qhi);
    cudaGetSymbolAddress((void**)&qlo, g_qlo);
    cudaGetSymbolAddress((void**)&khi, g_khi);
    cudaGetSymbolAddress((void**)&klo, g_klo);
    cudaGetSymbolAddress((void**)&vh,  g_vh);

    cudaFuncSetAttribute(qk_kernel, cudaFuncAttributeMaxDynamicSharedMemorySize, QK_SMEM);
    cudaFuncSetAttribute(pv_kernel, cudaFuncAttributeMaxDynamicSharedMemorySize, PV_SMEM);

    const int nv4 = (int)((size_t)BATCH * TQ * DIM / 4 / 256);  // 16384 blocks
    split_q_kernel<<<nv4, 256>>>(q, qhi, qlo);
    split_k_kernel<<<nv4, 256>>>(key, khi, klo, vh);

    dim3 g1(TK / 128, TQ / 128, BATCH);
    qk_kernel<<<g1, 256, QK_SMEM>>>((const uint16_t*)qhi, (const uint16_t*)qlo,
                                    (const uint16_t*)khi, (const uint16_t*)klo, energy);

    softmax_f16_kernel<<<BATCH * TQ, 256>>>(energy, ph);

    dim3 g2(DIM / 128, TQ / 128, BATCH);
    pv_kernel<<<g2, 256, PV_SMEM>>>((const uint16_t*)ph, (const uint16_t*)vh, out);
}